// round 2
// baseline (speedup 1.0000x reference)
#include <cuda_runtime.h>
#include <math.h>

// ---------------------------------------------------------------------------
// EBT_GRC beam-search tree composition. N=256, S=32, D=512, CH=2048, BEAM=5.
// Row-pool + index arrays; per-step fp32 GEMMs using packed fma.rn.f32x2.
// ---------------------------------------------------------------------------

#define NB    256
#define SEQ   32
#define DIM   512
#define CH    2048
#define BEAMK 5
#define MAXR  192
#define NTASK (NB * BEAMK)

typedef unsigned long long ull;

__device__ float g_rows[NB * MAXR * DIM];
__device__ float g_u  [NB * MAXR * DIM];
__device__ float g_v  [NB * MAXR * DIM];
__device__ float g_tmp[NB * SEQ * DIM];
__device__ float g_hcat[NTASK * CH];
__device__ float g_cc  [NTASK * CH];
__device__ int   g_idx [NB * BEAMK * SEQ];
__device__ float g_accu[NB * BEAMK];
__device__ int   g_task_l[NTASK];
__device__ int   g_task_r[NTASK];

__device__ __forceinline__ float gelu_f(float x) {
    return 0.5f * x * (1.0f + erff(x * 0.70710678118654752440f));
}
__device__ __forceinline__ ull dup2(float x) {
    ull r; asm("mov.b64 %0, {%1, %1};" : "=l"(r) : "f"(x)); return r;
}
__device__ __forceinline__ void fma2(ull &acc, ull a, ull b) {
    asm("fma.rn.f32x2 %0, %1, %2, %0;" : "+l"(acc) : "l"(a), "l"(b));
}
__device__ __forceinline__ float2 unp2(ull v) {
    float2 f; asm("mov.b64 {%0, %1}, %2;" : "=f"(f.x), "=f"(f.y) : "l"(v)); return f;
}

// ------------------------------- GEMM --------------------------------------
// 128x128 tile, BK=16, 256 threads, 8x8 per thread via packed f32x2 FMA.
#define BM 128
#define BN 128
#define BK 16
#define LDA (BM + 4)   // 132 floats per shared row (16B-aligned fragments)
#define LDBS (BN + 4)

// inner product core on shared tiles
__device__ __forceinline__ void mma_tile(
    const float (*As)[LDA], const float (*Bs)[LDBS],
    int ty, int tx, ull acc[4][8])
{
#pragma unroll
    for (int k = 0; k < BK; k++) {
        ulonglong2 aL = *(const ulonglong2*)&As[k][ty * 8];
        ulonglong2 aH = *(const ulonglong2*)&As[k][ty * 8 + 4];
        float4 b0 = *(const float4*)&Bs[k][tx * 8];
        float4 b1 = *(const float4*)&Bs[k][tx * 8 + 4];
        ull a01 = aL.x, a23 = aL.y, a45 = aH.x, a67 = aH.y;
        ull bd[8];
        bd[0] = dup2(b0.x); bd[1] = dup2(b0.y); bd[2] = dup2(b0.z); bd[3] = dup2(b0.w);
        bd[4] = dup2(b1.x); bd[5] = dup2(b1.y); bd[6] = dup2(b1.z); bd[7] = dup2(b1.w);
#pragma unroll
        for (int j = 0; j < 8; j++) {
            fma2(acc[0][j], a01, bd[j]);
            fma2(acc[1][j], a23, bd[j]);
            fma2(acc[2][j], a45, bd[j]);
            fma2(acc[3][j], a67, bd[j]);
        }
    }
}

// Generic GEMM: C[M,N] = act(A[M,K] @ B[K,N] + bias)
// a_mode/c_mode: 0 = contiguous, 1 = row-pool (row(m) = (m/rpn)*MAXR+base+m%rpn)
// n_split: if >0 and this block's n0 >= n_split, switch to Bw2/Cc2 (fused u/v).
__global__ __launch_bounds__(256) void gemm_kernel(
    const float* __restrict__ A, const float* __restrict__ Bw,
    const float* __restrict__ bias, float* __restrict__ Cc,
    int K, int lda, int ldb, int ldc,
    int a_mode, int a_base, int a_rpn,
    int c_mode, int c_base, int c_rpn, int act,
    const float* __restrict__ Bw2, float* __restrict__ Cc2, int n_split)
{
    __shared__ float As[BK][LDA];
    __shared__ float Bs[BK][LDBS];
    const int tid = threadIdx.x;
    const int m0 = blockIdx.y * BM;
    int n0 = blockIdx.x * BN;
    if (n_split && n0 >= n_split) { Bw = Bw2; Cc = Cc2; n0 -= n_split; }
    const int tx = tid & 15;
    const int ty = tid >> 4;

    // A loader: thread -> row m0 + (tid>>1), k-offset (tid&1)*8
    const int a_m = tid >> 1;
    const int a_k = (tid & 1) << 3;
    const float* arow;
    {
        int m = m0 + a_m;
        if (a_mode == 0) arow = A + (size_t)m * lda;
        else { int n = m / a_rpn; int r = m - n * a_rpn;
               arow = A + ((size_t)n * MAXR + a_base + r) * DIM; }
    }
    // B loader: thread -> k row (tid>>4), col (tid&15)*8
    const int b_k = tid >> 4;
    const int b_j = (tid & 15) << 3;
    const float* bptr = Bw + (size_t)b_k * ldb + n0 + b_j;

    ull acc[4][8];
#pragma unroll
    for (int i = 0; i < 4; i++)
#pragma unroll
        for (int j = 0; j < 8; j++) acc[i][j] = 0ull;

    for (int k0 = 0; k0 < K; k0 += BK) {
        float4 av0 = *(const float4*)(arow + k0 + a_k);
        float4 av1 = *(const float4*)(arow + k0 + a_k + 4);
        float4 bv0 = *(const float4*)(bptr + (size_t)k0 * ldb);
        float4 bv1 = *(const float4*)(bptr + (size_t)k0 * ldb + 4);
        if (k0) __syncthreads();
        As[a_k + 0][a_m] = av0.x; As[a_k + 1][a_m] = av0.y;
        As[a_k + 2][a_m] = av0.z; As[a_k + 3][a_m] = av0.w;
        As[a_k + 4][a_m] = av1.x; As[a_k + 5][a_m] = av1.y;
        As[a_k + 6][a_m] = av1.z; As[a_k + 7][a_m] = av1.w;
        *(float4*)&Bs[b_k][b_j]     = bv0;
        *(float4*)&Bs[b_k][b_j + 4] = bv1;
        __syncthreads();
        mma_tile(As, Bs, ty, tx, acc);
    }

    float4 bi0 = make_float4(0.f, 0.f, 0.f, 0.f), bi1 = bi0;
    if (bias) {
        bi0 = *(const float4*)(bias + n0 + tx * 8);
        bi1 = *(const float4*)(bias + n0 + tx * 8 + 4);
    }
    const float bb[8] = {bi0.x, bi0.y, bi0.z, bi0.w, bi1.x, bi1.y, bi1.z, bi1.w};
#pragma unroll
    for (int p = 0; p < 4; p++) {
        float r0[8], r1[8];
#pragma unroll
        for (int j = 0; j < 8; j++) {
            float2 f = unp2(acc[p][j]);
            r0[j] = f.x + bb[j]; r1[j] = f.y + bb[j];
            if (act) { r0[j] = gelu_f(r0[j]); r1[j] = gelu_f(r1[j]); }
        }
#pragma unroll
        for (int h = 0; h < 2; h++) {
            int m = m0 + ty * 8 + 2 * p + h;
            float* crow;
            if (c_mode == 0) crow = Cc + (size_t)m * ldc;
            else { int n = m / c_rpn; int r = m - n * c_rpn;
                   crow = Cc + ((size_t)n * MAXR + c_base + r) * DIM; }
            const float* rr = h ? r1 : r0;
            *(float4*)(crow + n0 + tx * 8)     = make_float4(rr[0], rr[1], rr[2], rr[3]);
            *(float4*)(crow + n0 + tx * 8 + 4) = make_float4(rr[4], rr[5], rr[6], rr[7]);
        }
    }
}

// cat-GEMM: A row t = [rows[l_t] | rows[r_t]] (K=1024) @ Wc1, gelu -> g_hcat
__global__ __launch_bounds__(256) void gemm_cat_kernel(
    const float* __restrict__ Wc1, const float* __restrict__ bc1)
{
    __shared__ float As[BK][LDA];
    __shared__ float Bs[BK][LDBS];
    const int tid = threadIdx.x;
    const int m0 = blockIdx.y * BM;
    const int n0 = blockIdx.x * BN;
    const int tx = tid & 15;
    const int ty = tid >> 4;

    const int a_m = tid >> 1;
    const int a_k = (tid & 1) << 3;
    const int t  = m0 + a_m;
    const int n  = t / BEAMK;
    const float* lrow = g_rows + ((size_t)n * MAXR + g_task_l[t]) * DIM;
    const float* rrow = g_rows + ((size_t)n * MAXR + g_task_r[t]) * DIM;

    const int b_k = tid >> 4;
    const int b_j = (tid & 15) << 3;
    const float* bptr = Wc1 + (size_t)b_k * CH + n0 + b_j;

    ull acc[4][8];
#pragma unroll
    for (int i = 0; i < 4; i++)
#pragma unroll
        for (int j = 0; j < 8; j++) acc[i][j] = 0ull;

    for (int k0 = 0; k0 < 2 * DIM; k0 += BK) {
        int kk = k0 + a_k;
        const float* src = (kk < DIM) ? (lrow + kk) : (rrow + kk - DIM);
        float4 av0 = *(const float4*)src;
        float4 av1 = *(const float4*)(src + 4);
        float4 bv0 = *(const float4*)(bptr + (size_t)k0 * CH);
        float4 bv1 = *(const float4*)(bptr + (size_t)k0 * CH + 4);
        if (k0) __syncthreads();
        As[a_k + 0][a_m] = av0.x; As[a_k + 1][a_m] = av0.y;
        As[a_k + 2][a_m] = av0.z; As[a_k + 3][a_m] = av0.w;
        As[a_k + 4][a_m] = av1.x; As[a_k + 5][a_m] = av1.y;
        As[a_k + 6][a_m] = av1.z; As[a_k + 7][a_m] = av1.w;
        *(float4*)&Bs[b_k][b_j]     = bv0;
        *(float4*)&Bs[b_k][b_j + 4] = bv1;
        __syncthreads();
        mma_tile(As, Bs, ty, tx, acc);
    }

    float4 bi0 = *(const float4*)(bc1 + n0 + tx * 8);
    float4 bi1 = *(const float4*)(bc1 + n0 + tx * 8 + 4);
    const float bb[8] = {bi0.x, bi0.y, bi0.z, bi0.w, bi1.x, bi1.y, bi1.z, bi1.w};
#pragma unroll
    for (int p = 0; p < 4; p++) {
        float r0[8], r1[8];
#pragma unroll
        for (int j = 0; j < 8; j++) {
            float2 f = unp2(acc[p][j]);
            r0[j] = gelu_f(f.x + bb[j]); r1[j] = gelu_f(f.y + bb[j]);
        }
#pragma unroll
        for (int h = 0; h < 2; h++) {
            int m = m0 + ty * 8 + 2 * p + h;
            float* crow = g_hcat + (size_t)m * CH;
            const float* rr = h ? r1 : r0;
            *(float4*)(crow + n0 + tx * 8)     = make_float4(rr[0], rr[1], rr[2], rr[3]);
            *(float4*)(crow + n0 + tx * 8 + 4) = make_float4(rr[4], rr[5], rr[6], rr[7]);
        }
    }
}

// ------------------------ selection (per batch elem) ------------------------
__global__ __launch_bounds__(256) void select_kernel(
    int B, int S_cur, int topk, int base_dest,
    const float* __restrict__ bd1, const float* __restrict__ Wd2,
    const float* __restrict__ bd2)
{
    const int n = blockIdx.x;
    const int tid = threadIdx.x;
    __shared__ float sw[BEAMK][SEQ];
    __shared__ int   sold[BEAMK][SEQ];
    __shared__ int   snew[BEAMK][SEQ];
    __shared__ float saccu[BEAMK];
    __shared__ float cscore[BEAMK * BEAMK];
    __shared__ int   cparent[BEAMK * BEAMK];
    __shared__ int   cpos[BEAMK * BEAMK];
    __shared__ int   ssel[BEAMK];
    __shared__ float snacc[BEAMK];
    __shared__ float sbd1[DIM];
    __shared__ float swd2[DIM];

    for (int t = tid; t < B * (S_cur + 1); t += 256) {
        int b = t / (S_cur + 1), s = t - b * (S_cur + 1);
        sold[b][s] = g_idx[(n * BEAMK + b) * SEQ + s];
    }
    for (int d = tid; d < DIM; d += 256) { sbd1[d] = bd1[d]; swd2[d] = Wd2[d]; }
    if (tid < B) saccu[tid] = g_accu[n * BEAMK + tid];
    __syncthreads();

    if (S_cur == 1) {
        if (tid < B) {
            g_task_l[n * BEAMK + tid] = sold[tid][0];
            g_task_r[n * BEAMK + tid] = sold[tid][1];
            g_idx[(n * BEAMK + tid) * SEQ] = base_dest + tid;
        }
        return;
    }

    const int lane = tid & 31, wid = tid >> 5;
    const float* un = g_u + (size_t)n * MAXR * DIM;
    const float* vn = g_v + (size_t)n * MAXR * DIM;
    for (int p = wid; p < B * S_cur; p += 8) {
        int b = p / S_cur, s = p - b * S_cur;
        const float* ul = un + (size_t)sold[b][s] * DIM;
        const float* vr = vn + (size_t)sold[b][s + 1] * DIM;
        float acc = 0.f;
        for (int d = lane; d < DIM; d += 32)
            acc += gelu_f(ul[d] + vr[d] + sbd1[d]) * swd2[d];
#pragma unroll
        for (int o = 16; o; o >>= 1) acc += __shfl_xor_sync(0xffffffffu, acc, o);
        if (lane == 0) sw[b][s] = acc + bd2[0];
    }
    __syncthreads();

    if (tid < B) {
        int b = tid;
        float m = -1e30f;
        for (int s = 0; s < S_cur; s++) m = fmaxf(m, sw[b][s]);
        float sum = 0.f;
        for (int s = 0; s < S_cur; s++) sum += expf(sw[b][s] - m);
        sum += 1e-20f;
        unsigned used = 0u;
        for (int k = 0; k < topk; k++) {
            float bv = -1e30f; int bi = 0;
            for (int s = 0; s < S_cur; s++) {
                if (used & (1u << s)) continue;
                if (sw[b][s] > bv) { bv = sw[b][s]; bi = s; }
            }
            used |= 1u << bi;
            float soft = expf(bv - m) / sum;
            cscore [b * topk + k] = saccu[b] + logf(soft + 1e-20f);
            cparent[b * topk + k] = b;
            cpos   [b * topk + k] = bi;
        }
    }
    __syncthreads();

    if (tid == 0) {
        int nc = B * topk;
        if (nc <= BEAMK) {
            for (int k = 0; k < nc; k++) ssel[k] = k;
        } else {
            unsigned used = 0u;
            for (int k = 0; k < BEAMK; k++) {
                float bv = -1e30f; int bi = 0;
                for (int c = 0; c < nc; c++) {
                    if (used & (1u << c)) continue;
                    if (cscore[c] > bv) { bv = cscore[c]; bi = c; }
                }
                used |= 1u << bi;
                ssel[k] = bi;
            }
        }
    }
    __syncthreads();

    if (tid < BEAMK) {
        int c = ssel[tid];
        snacc[tid] = cscore[c];
        int p = cparent[c], j = cpos[c];
        g_task_l[n * BEAMK + tid] = sold[p][j];
        g_task_r[n * BEAMK + tid] = sold[p][j + 1];
    }
    __syncthreads();
    for (int t = tid; t < BEAMK * S_cur; t += 256) {
        int k = t / S_cur, s = t - k * S_cur;
        int c = ssel[k]; int p = cparent[c], j = cpos[c];
        snew[k][s] = (s < j) ? sold[p][s] : (s == j ? base_dest + k : sold[p][s + 1]);
    }
    __syncthreads();
    for (int t = tid; t < BEAMK * S_cur; t += 256) {
        int k = t / S_cur, s = t - k * S_cur;
        g_idx[(n * BEAMK + k) * SEQ + s] = snew[k][s];
    }
    if (tid < BEAMK) g_accu[n * BEAMK + tid] = snacc[tid];
}

// ---------------------- gating + layernorm epilogue -------------------------
__global__ __launch_bounds__(256) void gate_ln_kernel(
    int base_dest, const float* __restrict__ gw, const float* __restrict__ bw)
{
    const int t = blockIdx.x;
    const int n = t / BEAMK;
    const int k = t - n * BEAMK;
    const int tid = threadIdx.x;
    const float* c    = g_cc   + (size_t)t * CH;
    const float* lrow = g_rows + ((size_t)n * MAXR + g_task_l[t]) * DIM;
    const float* rrow = g_rows + ((size_t)n * MAXR + g_task_r[t]) * DIM;
    __shared__ float sout[DIM];
    __shared__ float red[2][8];
    float lsum = 0.f, lsq = 0.f;
#pragma unroll
    for (int it = 0; it < 2; it++) {
        int d = tid + it * 256;
        float c0 = c[d], c1 = c[DIM + d], c2 = c[2 * DIM + d], c3 = c[3 * DIM + d];
        float mx = fmaxf(c0, fmaxf(c1, c2));
        float e0 = expf(c0 - mx), e1 = expf(c1 - mx), e2 = expf(c2 - mx);
        float inv = 1.0f / (e0 + e1 + e2);
        float o = (e0 * lrow[d] + e1 * rrow[d] + e2 * c3) * inv;
        sout[d] = o; lsum += o; lsq += o * o;
    }
#pragma unroll
    for (int o = 16; o; o >>= 1) {
        lsum += __shfl_xor_sync(0xffffffffu, lsum, o);
        lsq  += __shfl_xor_sync(0xffffffffu, lsq , o);
    }
    if ((tid & 31) == 0) { red[0][tid >> 5] = lsum; red[1][tid >> 5] = lsq; }
    __syncthreads();
    if (tid < 32) {
        float a = (tid < 8) ? red[0][tid] : 0.f;
        float b = (tid < 8) ? red[1][tid] : 0.f;
#pragma unroll
        for (int o = 4; o; o >>= 1) {
            a += __shfl_xor_sync(0xffffffffu, a, o);
            b += __shfl_xor_sync(0xffffffffu, b, o);
        }
        if (tid == 0) { red[0][0] = a; red[1][0] = b; }
    }
    __syncthreads();
    float mu   = red[0][0] * (1.0f / DIM);
    float var  = red[1][0] * (1.0f / DIM) - mu * mu;
    float rstd = rsqrtf(var + 1e-5f);
    float* outr = g_rows + ((size_t)n * MAXR + base_dest + k) * DIM;
#pragma unroll
    for (int it = 0; it < 2; it++) {
        int d = tid + it * 256;
        outr[d] = (sout[d] - mu) * rstd * gw[d] + bw[d];
    }
}

// --------------------- init: layernorm of x@Wi+bi ---------------------------
__global__ __launch_bounds__(256) void ln_init_kernel(
    const float* __restrict__ gw, const float* __restrict__ bw)
{
    const int t = blockIdx.x;
    const int n = t >> 5, s = t & 31;
    const int tid = threadIdx.x;
    const float* in = g_tmp + (size_t)t * DIM;
    float* outr = g_rows + ((size_t)n * MAXR + s) * DIM;
    __shared__ float red[2][8];
    float v0 = in[tid], v1 = in[tid + 256];
    float lsum = v0 + v1, lsq = v0 * v0 + v1 * v1;
#pragma unroll
    for (int o = 16; o; o >>= 1) {
        lsum += __shfl_xor_sync(0xffffffffu, lsum, o);
        lsq  += __shfl_xor_sync(0xffffffffu, lsq , o);
    }
    if ((tid & 31) == 0) { red[0][tid >> 5] = lsum; red[1][tid >> 5] = lsq; }
    __syncthreads();
    if (tid < 32) {
        float a = (tid < 8) ? red[0][tid] : 0.f;
        float b = (tid < 8) ? red[1][tid] : 0.f;
#pragma unroll
        for (int o = 4; o; o >>= 1) {
            a += __shfl_xor_sync(0xffffffffu, a, o);
            b += __shfl_xor_sync(0xffffffffu, b, o);
        }
        if (tid == 0) { red[0][0] = a; red[1][0] = b; }
    }
    __syncthreads();
    float mu   = red[0][0] * (1.0f / DIM);
    float var  = red[1][0] * (1.0f / DIM) - mu * mu;
    float rstd = rsqrtf(var + 1e-5f);
    outr[tid]       = (v0 - mu) * rstd * gw[tid]       + bw[tid];
    outr[tid + 256] = (v1 - mu) * rstd * gw[tid + 256] + bw[tid + 256];
}

__global__ void init_state_kernel()
{
    int n = blockIdx.x;
    if (threadIdx.x < SEQ) g_idx[n * BEAMK * SEQ + threadIdx.x] = threadIdx.x;
    if (threadIdx.x == 0) g_accu[n * BEAMK] = 0.f;
}

__global__ __launch_bounds__(256) void final_kernel(float* __restrict__ out)
{
    const int n = blockIdx.x;
    const int tid = threadIdx.x;
    __shared__ float wts[BEAMK];
    __shared__ int   rid[BEAMK];
    if (tid < BEAMK) rid[tid] = g_idx[(n * BEAMK + tid) * SEQ];
    if (tid == 0) {
        float a[BEAMK]; float m = -1e30f;
        for (int b = 0; b < BEAMK; b++) { a[b] = g_accu[n * BEAMK + b]; m = fmaxf(m, a[b]); }
        float s = 0.f;
        for (int b = 0; b < BEAMK; b++) { a[b] = expf(a[b] - m); s += a[b]; }
        for (int b = 0; b < BEAMK; b++) wts[b] = a[b] / s;
    }
    __syncthreads();
#pragma unroll
    for (int it = 0; it < 2; it++) {
        int d = tid + it * 256;
        float acc = 0.f;
        for (int b = 0; b < BEAMK; b++)
            acc += wts[b] * g_rows[((size_t)n * MAXR + rid[b]) * DIM + d];
        out[n * DIM + d] = acc;
    }
}

// --------------------------------- host ------------------------------------
extern "C" void kernel_launch(void* const* d_in, const int* in_sizes, int n_in,
                              void* d_out, int out_size)
{
    const float* x   = (const float*)d_in[0];
    const float* Wi  = (const float*)d_in[2];
    const float* bi  = (const float*)d_in[3];
    const float* g1  = (const float*)d_in[4];
    const float* b1  = (const float*)d_in[5];
    const float* Wd1 = (const float*)d_in[6];
    const float* bd1 = (const float*)d_in[7];
    const float* Wd2 = (const float*)d_in[8];
    const float* bd2 = (const float*)d_in[9];
    const float* Wc1 = (const float*)d_in[10];
    const float* bc1 = (const float*)d_in[11];
    const float* Wc2 = (const float*)d_in[12];
    const float* bc2 = (const float*)d_in[13];
    const float* g2  = (const float*)d_in[14];
    const float* b2  = (const float*)d_in[15];
    float* out = (float*)d_out;

    float *rows_p, *u_p, *v_p, *tmp_p, *hcat_p, *c_p;
    cudaGetSymbolAddress((void**)&rows_p, g_rows);
    cudaGetSymbolAddress((void**)&u_p,    g_u);
    cudaGetSymbolAddress((void**)&v_p,    g_v);
    cudaGetSymbolAddress((void**)&tmp_p,  g_tmp);
    cudaGetSymbolAddress((void**)&hcat_p, g_hcat);
    cudaGetSymbolAddress((void**)&c_p,    g_cc);

    dim3 blk(256);

    // init: tmp = x@Wi+bi ; rows = LN(tmp) ; u,v caches for initial rows
    gemm_kernel<<<dim3(DIM / BN, (NB * SEQ) / BM), blk>>>(
        x, Wi, bi, tmp_p, DIM, DIM, DIM, DIM,
        0, 0, 0, 0, 0, 0, 0, nullptr, nullptr, 0);
    ln_init_kernel<<<NB * SEQ, blk>>>(g1, b1);
    init_state_kernel<<<NB, 32>>>();
    // fused u/v projection of the 32 initial rows per n
    gemm_kernel<<<dim3(2 * DIM / BN, (NB * SEQ) / BM), blk>>>(
        rows_p, Wd1, nullptr, u_p, DIM, 0, DIM, 0,
        1, 0, SEQ, 1, 0, SEQ, 0,
        Wd1 + DIM * DIM, v_p, DIM);

    for (int step = 0; step < SEQ - 1; step++) {
        int S_cur = (SEQ - 1) - step;
        int B = (step == 0) ? 1 : BEAMK;
        int topk = S_cur < BEAMK ? S_cur : BEAMK;
        int base = SEQ + step * BEAMK;

        select_kernel<<<NB, blk>>>(B, S_cur, topk, base, bd1, Wd2, bd2);
        gemm_cat_kernel<<<dim3(CH / BN, NTASK / BM), blk>>>(Wc1, bc1);
        gemm_kernel<<<dim3(CH / BN, NTASK / BM), blk>>>(
            hcat_p, Wc2, bc2, c_p, CH, CH, CH, CH,
            0, 0, 0, 0, 0, 0, 0, nullptr, nullptr, 0);
        gate_ln_kernel<<<NTASK, blk>>>(base, g2, b2);
        if (step < SEQ - 2) {
            gemm_kernel<<<dim3(2 * DIM / BN, NTASK / BM), blk>>>(
                rows_p, Wd1, nullptr, u_p, DIM, 0, DIM, 0,
                1, base, BEAMK, 1, base, BEAMK, 0,
                Wd1 + DIM * DIM, v_p, DIM);
        }
    }

    final_kernel<<<NB, blk>>>(out);
    (void)in_sizes; (void)n_in; (void)out_size;
}

// round 6
// speedup vs baseline: 1.5009x; 1.5009x over previous
#include <cuda_runtime.h>
#include <cuda_bf16.h>
#include <math.h>
#include <stdint.h>

// ---------------------------------------------------------------------------
// EBT_GRC beam search. N=256, S=32, D=512, CH=2048, BEAM=5.
// All GEMMs: bf16 triple-split (3 planes/operand, 6 cross-products) on
// mma.sync.m16n8k16 tensor cores => fp32-equivalent accuracy.
// ---------------------------------------------------------------------------

#define NB    256
#define SEQ   32
#define DIM   512
#define CH    2048
#define BEAMK 5
#define MAXR  192
#define NTASK (NB * BEAMK)

typedef __nv_bfloat16 bhalf;

// fp32 state
__device__ float g_rows[NB * MAXR * DIM];
__device__ float g_u  [NB * MAXR * DIM];
__device__ float g_v  [NB * MAXR * DIM];
__device__ float g_tmp[NB * SEQ * DIM];
__device__ float g_cc [NTASK * CH];
__device__ int   g_idx [NB * BEAMK * SEQ];
__device__ float g_accu[NB * BEAMK];
__device__ int   g_task_l[NTASK];
__device__ int   g_task_r[NTASK];
// bf16 triple-split planes
__device__ bhalf g_rp0[NB * MAXR * DIM], g_rp1[NB * MAXR * DIM], g_rp2[NB * MAXR * DIM];
__device__ bhalf g_xp0[NB * SEQ * DIM],  g_xp1[NB * SEQ * DIM],  g_xp2[NB * SEQ * DIM];
__device__ bhalf g_hp0[NTASK * CH],      g_hp1[NTASK * CH],      g_hp2[NTASK * CH];
__device__ bhalf g_wi0[DIM * DIM],       g_wi1[DIM * DIM],       g_wi2[DIM * DIM];
__device__ bhalf g_wdp0[DIM * 2 * DIM],  g_wdp1[DIM * 2 * DIM],  g_wdp2[DIM * 2 * DIM];
__device__ bhalf g_wc1p0[2 * DIM * CH],  g_wc1p1[2 * DIM * CH],  g_wc1p2[2 * DIM * CH];
__device__ bhalf g_wc2p0[CH * CH],       g_wc2p1[CH * CH],       g_wc2p2[CH * CH];

__device__ __forceinline__ float gelu_f(float xval) {
    return 0.5f * xval * (1.0f + erff(xval * 0.70710678118654752440f));
}
__device__ __forceinline__ void split3(float xval, unsigned short &qs0,
                                       unsigned short &qs1, unsigned short &qs2) {
    bhalf h0 = __float2bfloat16(xval);
    float r0 = __bfloat162float(h0);
    bhalf h1 = __float2bfloat16(xval - r0);
    float r1 = __bfloat162float(h1);
    bhalf h2 = __float2bfloat16(xval - r0 - r1);
    qs0 = __bfloat16_as_ushort(h0);
    qs1 = __bfloat16_as_ushort(h1);
    qs2 = __bfloat16_as_ushort(h2);
}

__device__ __forceinline__ void ldmA(uint32_t regs[4], uint32_t addr) {
    asm volatile("ldmatrix.sync.aligned.m8n8.x4.shared.b16 {%0,%1,%2,%3}, [%4];"
        : "=r"(regs[0]), "=r"(regs[1]), "=r"(regs[2]), "=r"(regs[3]) : "r"(addr));
}
__device__ __forceinline__ void ldmBT(uint32_t regs[4], uint32_t addr) {
    asm volatile("ldmatrix.sync.aligned.m8n8.x4.trans.shared.b16 {%0,%1,%2,%3}, [%4];"
        : "=r"(regs[0]), "=r"(regs[1]), "=r"(regs[2]), "=r"(regs[3]) : "r"(addr));
}
__device__ __forceinline__ void mma16816(float cfr[4], const uint32_t afr[4],
                                         uint32_t rblo, uint32_t rbhi) {
    asm volatile(
        "mma.sync.aligned.m16n8k16.row.col.f32.bf16.bf16.f32 "
        "{%0,%1,%2,%3}, {%4,%5,%6,%7}, {%8,%9}, {%0,%1,%2,%3};"
        : "+f"(cfr[0]), "+f"(cfr[1]), "+f"(cfr[2]), "+f"(cfr[3])
        : "r"(afr[0]), "r"(afr[1]), "r"(afr[2]), "r"(afr[3]), "r"(rblo), "r"(rbhi));
}

// ------------------------------ mma GEMM ------------------------------------
// Tile 128x128x32, 512 threads (16 warps, 4m x 4n), warp tile 32x32.
#define BM 128
#define BN 128
#define BK 32
#define BKP 40     // A smem row stride (bf16)
#define BNP 136    // B smem row stride (bf16)
#define PLA (BM * BKP)
#define PLB (BK * BNP)
#define SMEM_BYTES ((3 * PLA + 3 * PLB) * 2)

// a_mode: 0 contiguous lda; 1 row-pool (base,rpn); 2 cat-gather (task_l/r, K=1024)
// c_mode: 0 fp32 contiguous ldc; 1 fp32 row-pool split at n_split (Cf/Cf2); 2 planes
__global__ __launch_bounds__(512) void gemm6(
    const bhalf* __restrict__ A0, const bhalf* __restrict__ A1, const bhalf* __restrict__ A2,
    const bhalf* __restrict__ B0, const bhalf* __restrict__ B1, const bhalf* __restrict__ B2,
    const float* __restrict__ bias, float* __restrict__ Cf, float* __restrict__ Cf2,
    bhalf* __restrict__ P0, bhalf* __restrict__ P1, bhalf* __restrict__ P2,
    int K, int lda, int ldb, int ldc,
    int a_mode, int a_base, int a_rpn,
    int c_mode, int c_base, int c_rpn, int act, int n_split)
{
    extern __shared__ __align__(16) bhalf smem[];
    bhalf* As = smem;               // [3][BM][BKP]
    bhalf* Bs = smem + 3 * PLA;     // [3][BK][BNP]

    const int tid = threadIdx.x;
    const int lane = tid & 31, wrp = tid >> 5;
    const int m0 = blockIdx.y * BM;
    const int n0b = blockIdx.x * BN;
    const int m_w = (wrp >> 2) * 32;
    const int n_w = (wrp & 3) * 32;

    int aoff[2], aoffR[2], asw[2];
    int boff[2], bsw[2];
#pragma unroll
    for (int i = 0; i < 2; i++) {
        int lin = tid + i * 512;
        int arow = lin >> 3, ks4 = (lin & 7) << 2;
        int mrow = m0 + arow;
        if (a_mode == 0) { aoff[i] = mrow * lda + ks4; aoffR[i] = 0; }
        else if (a_mode == 1) {
            int nz = mrow / a_rpn, rr = mrow - nz * a_rpn;
            aoff[i] = (nz * MAXR + a_base + rr) * DIM + ks4; aoffR[i] = 0;
        } else {
            int nz = mrow / BEAMK;
            aoff[i]  = (nz * MAXR + g_task_l[mrow]) * DIM + ks4;
            aoffR[i] = (nz * MAXR + g_task_r[mrow]) * DIM + ks4;
        }
        asw[i] = arow * BKP + ks4;
        int brow = lin >> 5, ns4 = (lin & 31) << 2;
        boff[i] = brow * ldb + n0b + ns4;
        bsw[i] = brow * BNP + ns4;
    }

    float acc[2][4][4];
#pragma unroll
    for (int mt = 0; mt < 2; mt++)
#pragma unroll
        for (int nt = 0; nt < 4; nt++)
#pragma unroll
            for (int qq = 0; qq < 4; qq++) acc[mt][nt][qq] = 0.f;

    const uint32_t sAs = (uint32_t)__cvta_generic_to_shared(As);
    const uint32_t sBs = (uint32_t)__cvta_generic_to_shared(Bs);

    uint2 pfA[2][3], pfB[2][3];
    auto load_stage = [&](int kbase) {
#pragma unroll
        for (int i = 0; i < 2; i++) {
            int aos;
            if (a_mode == 2)
                aos = (kbase < DIM) ? (aoff[i] + kbase) : (aoffR[i] + (kbase - DIM));
            else
                aos = aoff[i] + kbase;
            pfA[i][0] = *(const uint2*)(A0 + aos);
            pfA[i][1] = *(const uint2*)(A1 + aos);
            pfA[i][2] = *(const uint2*)(A2 + aos);
            int bos = boff[i] + kbase * ldb;
            pfB[i][0] = *(const uint2*)(B0 + bos);
            pfB[i][1] = *(const uint2*)(B1 + bos);
            pfB[i][2] = *(const uint2*)(B2 + bos);
        }
    };

    load_stage(0);
    for (int k0 = 0; k0 < K; k0 += BK) {
#pragma unroll
        for (int i = 0; i < 2; i++) {
#pragma unroll
            for (int pl = 0; pl < 3; pl++) {
                *(uint2*)(As + pl * PLA + asw[i]) = pfA[i][pl];
                *(uint2*)(Bs + pl * PLB + bsw[i]) = pfB[i][pl];
            }
        }
        __syncthreads();
        if (k0 + BK < K) load_stage(k0 + BK);

        const int lrow16 = lane & 15, lcol8 = (lane >> 4) << 3;
#pragma unroll
        for (int ks = 0; ks < 2; ks++) {
#pragma unroll
            for (int pA = 0; pA < 3; pA++) {
                uint32_t frag_a[2][4];
#pragma unroll
                for (int mt = 0; mt < 2; mt++)
                    ldmA(frag_a[mt], sAs + ((pA * BM + m_w + mt * 16 + lrow16) * BKP
                                            + ks * 16 + lcol8) * 2);
#pragma unroll
                for (int pB = 0; pB < 3; pB++) {
                    if (pA + pB < 3) {
                        uint32_t frag_b[2][4];
#pragma unroll
                        for (int nb = 0; nb < 2; nb++)
                            ldmBT(frag_b[nb], sBs + ((pB * BK + ks * 16 + lrow16) * BNP
                                                     + n_w + nb * 16 + lcol8) * 2);
#pragma unroll
                        for (int mt = 0; mt < 2; mt++)
#pragma unroll
                            for (int nt = 0; nt < 4; nt++)
                                mma16816(acc[mt][nt], frag_a[mt],
                                         frag_b[nt >> 1][(nt & 1) * 2],
                                         frag_b[nt >> 1][(nt & 1) * 2 + 1]);
                    }
                }
            }
        }
        __syncthreads();
    }

    // ------------------------------ epilogue --------------------------------
    float* Cfx = Cf;
    int n0c = n0b;
    if (c_mode == 1 && n0b >= n_split) { Cfx = Cf2; n0c = n0b - n_split; }

    const int grp = lane >> 2, tc2 = (lane & 3) * 2;
#pragma unroll
    for (int mt = 0; mt < 2; mt++) {
#pragma unroll
        for (int nt = 0; nt < 4; nt++) {
            int coln = n_w + nt * 8 + tc2;
            float2 bv = make_float2(0.f, 0.f);
            if (bias) bv = *(const float2*)(bias + n0b + coln);
            float vals[2][2];
            vals[0][0] = acc[mt][nt][0] + bv.x; vals[0][1] = acc[mt][nt][1] + bv.y;
            vals[1][0] = acc[mt][nt][2] + bv.x; vals[1][1] = acc[mt][nt][3] + bv.y;
            if (act) {
#pragma unroll
                for (int hh = 0; hh < 2; hh++) {
                    vals[hh][0] = gelu_f(vals[hh][0]);
                    vals[hh][1] = gelu_f(vals[hh][1]);
                }
            }
#pragma unroll
            for (int hh = 0; hh < 2; hh++) {
                int mrow = m0 + m_w + mt * 16 + grp + hh * 8;
                if (c_mode == 2) {
                    size_t off = (size_t)mrow * ldc + n0b + coln;
                    unsigned short plo0, plo1, plo2, phi0, phi1, phi2;
                    split3(vals[hh][0], plo0, plo1, plo2);
                    split3(vals[hh][1], phi0, phi1, phi2);
                    *(uint32_t*)(P0 + off) = (uint32_t)plo0 | ((uint32_t)phi0 << 16);
                    *(uint32_t*)(P1 + off) = (uint32_t)plo1 | ((uint32_t)phi1 << 16);
                    *(uint32_t*)(P2 + off) = (uint32_t)plo2 | ((uint32_t)phi2 << 16);
                } else if (c_mode == 1) {
                    int nz = mrow / c_rpn, rr = mrow - nz * c_rpn;
                    float* cp = Cfx + ((size_t)nz * MAXR + c_base + rr) * DIM + n0c + coln;
                    *(float2*)cp = make_float2(vals[hh][0], vals[hh][1]);
                } else {
                    float* cp = Cfx + (size_t)mrow * ldc + n0b + coln;
                    *(float2*)cp = make_float2(vals[hh][0], vals[hh][1]);
                }
            }
        }
    }
}

// --------------------------- pack kernels -----------------------------------
__global__ void pack3_kernel(const float* __restrict__ src,
                             bhalf* __restrict__ dst0, bhalf* __restrict__ dst1,
                             bhalf* __restrict__ dst2, int nelem)
{
    for (int i = blockIdx.x * blockDim.x + threadIdx.x; i < nelem;
         i += gridDim.x * blockDim.x) {
        unsigned short qs0, qs1, qs2;
        split3(src[i], qs0, qs1, qs2);
        dst0[i] = __ushort_as_bfloat16(qs0);
        dst1[i] = __ushort_as_bfloat16(qs1);
        dst2[i] = __ushort_as_bfloat16(qs2);
    }
}
// Wd1 (1024,512) -> B' [512][1024]: B'[k][n] = Wd1[(n<512?k:512+k)][n&511]
__global__ void pack3_wd1_kernel(const float* __restrict__ src,
                                 bhalf* __restrict__ dst0, bhalf* __restrict__ dst1,
                                 bhalf* __restrict__ dst2)
{
    for (int i = blockIdx.x * blockDim.x + threadIdx.x; i < DIM * 2 * DIM;
         i += gridDim.x * blockDim.x) {
        int krow = i >> 10, ncol = i & 1023;
        float xval = src[(ncol < DIM ? krow : DIM + krow) * DIM + (ncol & (DIM - 1))];
        unsigned short qs0, qs1, qs2;
        split3(xval, qs0, qs1, qs2);
        dst0[i] = __ushort_as_bfloat16(qs0);
        dst1[i] = __ushort_as_bfloat16(qs1);
        dst2[i] = __ushort_as_bfloat16(qs2);
    }
}

// ------------------------ selection (per batch elem) ------------------------
__global__ __launch_bounds__(256) void select_kernel(
    int Bc, int S_cur, int topk, int base_dest,
    const float* __restrict__ bd1, const float* __restrict__ Wd2,
    const float* __restrict__ bd2)
{
    const int nn = blockIdx.x;
    const int tid = threadIdx.x;
    __shared__ float sw[BEAMK][SEQ];
    __shared__ int   sold[BEAMK][SEQ];
    __shared__ int   snew[BEAMK][SEQ];
    __shared__ float saccu[BEAMK];
    __shared__ float cscore[BEAMK * BEAMK];
    __shared__ int   cparent[BEAMK * BEAMK];
    __shared__ int   cpos[BEAMK * BEAMK];
    __shared__ int   ssel[BEAMK];
    __shared__ float snacc[BEAMK];
    __shared__ float sbd1[DIM];
    __shared__ float swd2[DIM];

    for (int t = tid; t < Bc * (S_cur + 1); t += 256) {
        int bb = t / (S_cur + 1), ss = t - bb * (S_cur + 1);
        sold[bb][ss] = g_idx[(nn * BEAMK + bb) * SEQ + ss];
    }
    for (int dd = tid; dd < DIM; dd += 256) { sbd1[dd] = bd1[dd]; swd2[dd] = Wd2[dd]; }
    if (tid < Bc) saccu[tid] = g_accu[nn * BEAMK + tid];
    __syncthreads();

    if (S_cur == 1) {
        if (tid < Bc) {
            g_task_l[nn * BEAMK + tid] = sold[tid][0];
            g_task_r[nn * BEAMK + tid] = sold[tid][1];
            g_idx[(nn * BEAMK + tid) * SEQ] = base_dest + tid;
        }
        return;
    }

    const int lane = tid & 31, wrp = tid >> 5;
    const float* un = g_u + (size_t)nn * MAXR * DIM;
    const float* vn = g_v + (size_t)nn * MAXR * DIM;
    for (int pp = wrp; pp < Bc * S_cur; pp += 8) {
        int bb = pp / S_cur, ss = pp - bb * S_cur;
        const float* ul = un + (size_t)sold[bb][ss] * DIM;
        const float* vr = vn + (size_t)sold[bb][ss + 1] * DIM;
        float accv = 0.f;
        for (int dd = lane; dd < DIM; dd += 32)
            accv += gelu_f(ul[dd] + vr[dd] + sbd1[dd]) * swd2[dd];
#pragma unroll
        for (int oo = 16; oo; oo >>= 1)
            accv += __shfl_xor_sync(0xffffffffu, accv, oo);
        if (lane == 0) sw[bb][ss] = accv + bd2[0];
    }
    __syncthreads();

    if (tid < Bc) {
        int bb = tid;
        float mx = -1e30f;
        for (int ss = 0; ss < S_cur; ss++) mx = fmaxf(mx, sw[bb][ss]);
        float sum = 0.f;
        for (int ss = 0; ss < S_cur; ss++) sum += expf(sw[bb][ss] - mx);
        sum += 1e-20f;
        unsigned used = 0u;
        for (int kk = 0; kk < topk; kk++) {
            float bestv = -1e30f; int besti = 0;
            for (int ss = 0; ss < S_cur; ss++) {
                if (used & (1u << ss)) continue;
                if (sw[bb][ss] > bestv) { bestv = sw[bb][ss]; besti = ss; }
            }
            used |= 1u << besti;
            float soft = expf(bestv - mx) / sum;
            cscore [bb * topk + kk] = saccu[bb] + logf(soft + 1e-20f);
            cparent[bb * topk + kk] = bb;
            cpos   [bb * topk + kk] = besti;
        }
    }
    __syncthreads();

    if (tid == 0) {
        int nc = Bc * topk;
        if (nc <= BEAMK) {
            for (int kk = 0; kk < nc; kk++) ssel[kk] = kk;
        } else {
            unsigned used = 0u;
            for (int kk = 0; kk < BEAMK; kk++) {
                float bestv = -1e30f; int besti = 0;
                for (int cc = 0; cc < nc; cc++) {
                    if (used & (1u << cc)) continue;
                    if (cscore[cc] > bestv) { bestv = cscore[cc]; besti = cc; }
                }
                used |= 1u << besti;
                ssel[kk] = besti;
            }
        }
    }
    __syncthreads();

    if (tid < BEAMK) {
        int cc = ssel[tid];
        snacc[tid] = cscore[cc];
        int pp = cparent[cc], jj = cpos[cc];
        g_task_l[nn * BEAMK + tid] = sold[pp][jj];
        g_task_r[nn * BEAMK + tid] = sold[pp][jj + 1];
    }
    __syncthreads();
    for (int t = tid; t < BEAMK * S_cur; t += 256) {
        int kk = t / S_cur, ss = t - kk * S_cur;
        int cc = ssel[kk]; int pp = cparent[cc], jj = cpos[cc];
        snew[kk][ss] = (ss < jj) ? sold[pp][ss]
                                 : (ss == jj ? base_dest + kk : sold[pp][ss + 1]);
    }
    __syncthreads();
    for (int t = tid; t < BEAMK * S_cur; t += 256) {
        int kk = t / S_cur, ss = t - kk * S_cur;
        g_idx[(nn * BEAMK + kk) * SEQ + ss] = snew[kk][ss];
    }
    if (tid < BEAMK) g_accu[nn * BEAMK + tid] = snacc[tid];
}

// ---------------------- gating + layernorm epilogue -------------------------
__global__ __launch_bounds__(256) void gate_ln_kernel(
    int base_dest, const float* __restrict__ gw, const float* __restrict__ bw)
{
    const int t = blockIdx.x;
    const int nn = t / BEAMK;
    const int kk = t - nn * BEAMK;
    const int tid = threadIdx.x;
    const float* cc   = g_cc   + (size_t)t * CH;
    const float* lrow = g_rows + ((size_t)nn * MAXR + g_task_l[t]) * DIM;
    const float* rrow = g_rows + ((size_t)nn * MAXR + g_task_r[t]) * DIM;
    __shared__ float sout[DIM];
    __shared__ float red[2][8];
    float lsum = 0.f, lsq = 0.f;
#pragma unroll
    for (int it = 0; it < 2; it++) {
        int dd = tid + it * 256;
        float c0v = cc[dd], c1v = cc[DIM + dd], c2v = cc[2 * DIM + dd], c3v = cc[3 * DIM + dd];
        float mx = fmaxf(c0v, fmaxf(c1v, c2v));
        float e0v = expf(c0v - mx), e1v = expf(c1v - mx), e2v = expf(c2v - mx);
        float inv = 1.0f / (e0v + e1v + e2v);
        float ov = (e0v * lrow[dd] + e1v * rrow[dd] + e2v * c3v) * inv;
        sout[dd] = ov; lsum += ov; lsq += ov * ov;
    }
#pragma unroll
    for (int oo = 16; oo; oo >>= 1) {
        lsum += __shfl_xor_sync(0xffffffffu, lsum, oo);
        lsq  += __shfl_xor_sync(0xffffffffu, lsq , oo);
    }
    if ((tid & 31) == 0) { red[0][tid >> 5] = lsum; red[1][tid >> 5] = lsq; }
    __syncthreads();
    if (tid < 32) {
        float ra = (tid < 8) ? red[0][tid] : 0.f;
        float rb = (tid < 8) ? red[1][tid] : 0.f;
#pragma unroll
        for (int oo = 4; oo; oo >>= 1) {
            ra += __shfl_xor_sync(0xffffffffu, ra, oo);
            rb += __shfl_xor_sync(0xffffffffu, rb, oo);
        }
        if (tid == 0) { red[0][0] = ra; red[1][0] = rb; }
    }
    __syncthreads();
    float mu   = red[0][0] * (1.0f / DIM);
    float var  = red[1][0] * (1.0f / DIM) - mu * mu;
    float rstd = rsqrtf(var + 1e-5f);
    size_t ro = ((size_t)nn * MAXR + base_dest + kk) * DIM;
#pragma unroll
    for (int it = 0; it < 2; it++) {
        int dd = tid + it * 256;
        float ov = (sout[dd] - mu) * rstd * gw[dd] + bw[dd];
        g_rows[ro + dd] = ov;
        unsigned short qs0, qs1, qs2;
        split3(ov, qs0, qs1, qs2);
        g_rp0[ro + dd] = __ushort_as_bfloat16(qs0);
        g_rp1[ro + dd] = __ushort_as_bfloat16(qs1);
        g_rp2[ro + dd] = __ushort_as_bfloat16(qs2);
    }
}

// --------------------- init: layernorm of x@Wi+bi ---------------------------
__global__ __launch_bounds__(256) void ln_init_kernel(
    const float* __restrict__ gw, const float* __restrict__ bw)
{
    const int t = blockIdx.x;
    const int nn = t >> 5, ss = t & 31;
    const int tid = threadIdx.x;
    const float* inp = g_tmp + (size_t)t * DIM;
    size_t ro = ((size_t)nn * MAXR + ss) * DIM;
    __shared__ float red[2][8];
    float v0 = inp[tid], v1 = inp[tid + 256];
    float lsum = v0 + v1, lsq = v0 * v0 + v1 * v1;
#pragma unroll
    for (int oo = 16; oo; oo >>= 1) {
        lsum += __shfl_xor_sync(0xffffffffu, lsum, oo);
        lsq  += __shfl_xor_sync(0xffffffffu, lsq , oo);
    }
    if ((tid & 31) == 0) { red[0][tid >> 5] = lsum; red[1][tid >> 5] = lsq; }
    __syncthreads();
    if (tid < 32) {
        float ra = (tid < 8) ? red[0][tid] : 0.f;
        float rb = (tid < 8) ? red[1][tid] : 0.f;
#pragma unroll
        for (int oo = 4; oo; oo >>= 1) {
            ra += __shfl_xor_sync(0xffffffffu, ra, oo);
            rb += __shfl_xor_sync(0xffffffffu, rb, oo);
        }
        if (tid == 0) { red[0][0] = ra; red[1][0] = rb; }
    }
    __syncthreads();
    float mu   = red[0][0] * (1.0f / DIM);
    float var  = red[1][0] * (1.0f / DIM) - mu * mu;
    float rstd = rsqrtf(var + 1e-5f);
#pragma unroll
    for (int it = 0; it < 2; it++) {
        int dd = tid + it * 256;
        float vv = it ? v1 : v0;
        float ov = (vv - mu) * rstd * gw[dd] + bw[dd];
        g_rows[ro + dd] = ov;
        unsigned short qs0, qs1, qs2;
        split3(ov, qs0, qs1, qs2);
        g_rp0[ro + dd] = __ushort_as_bfloat16(qs0);
        g_rp1[ro + dd] = __ushort_as_bfloat16(qs1);
        g_rp2[ro + dd] = __ushort_as_bfloat16(qs2);
    }
}

__global__ void init_state_kernel()
{
    int nn = blockIdx.x;
    if (threadIdx.x < SEQ) g_idx[nn * BEAMK * SEQ + threadIdx.x] = threadIdx.x;
    if (threadIdx.x == 0) g_accu[nn * BEAMK] = 0.f;
}

__global__ __launch_bounds__(256) void final_kernel(float* __restrict__ outp)
{
    const int nn = blockIdx.x;
    const int tid = threadIdx.x;
    __shared__ float wts[BEAMK];
    __shared__ int   rid[BEAMK];
    if (tid < BEAMK) rid[tid] = g_idx[(nn * BEAMK + tid) * SEQ];
    if (tid == 0) {
        float av[BEAMK]; float mx = -1e30f;
        for (int bb = 0; bb < BEAMK; bb++) {
            av[bb] = g_accu[nn * BEAMK + bb]; mx = fmaxf(mx, av[bb]);
        }
        float sm = 0.f;
        for (int bb = 0; bb < BEAMK; bb++) { av[bb] = expf(av[bb] - mx); sm += av[bb]; }
        for (int bb = 0; bb < BEAMK; bb++) wts[bb] = av[bb] / sm;
    }
    __syncthreads();
#pragma unroll
    for (int it = 0; it < 2; it++) {
        int dd = tid + it * 256;
        float accv = 0.f;
        for (int bb = 0; bb < BEAMK; bb++)
            accv += wts[bb] * g_rows[((size_t)nn * MAXR + rid[bb]) * DIM + dd];
        outp[nn * DIM + dd] = accv;
    }
}

// --------------------------------- host ------------------------------------
extern "C" void kernel_launch(void* const* d_in, const int* in_sizes, int n_in,
                              void* d_out, int out_size)
{
    const float* x   = (const float*)d_in[0];
    const float* Wi  = (const float*)d_in[2];
    const float* bi  = (const float*)d_in[3];
    const float* g1  = (const float*)d_in[4];
    const float* b1  = (const float*)d_in[5];
    const float* Wd1 = (const float*)d_in[6];
    const float* bd1 = (const float*)d_in[7];
    const float* Wd2 = (const float*)d_in[8];
    const float* bd2 = (const float*)d_in[9];
    const float* Wc1 = (const float*)d_in[10];
    const float* bc1 = (const float*)d_in[11];
    const float* Wc2 = (const float*)d_in[12];
    const float* bc2 = (const float*)d_in[13];
    const float* g2  = (const float*)d_in[14];
    const float* b2  = (const float*)d_in[15];
    float* outp = (float*)d_out;

    cudaFuncSetAttribute(gemm6, cudaFuncAttributeMaxDynamicSharedMemorySize,
                         SMEM_BYTES);

    float *tmp_p, *u_p, *v_p, *cc_p;
    cudaGetSymbolAddress((void**)&tmp_p, g_tmp);
    cudaGetSymbolAddress((void**)&u_p,   g_u);
    cudaGetSymbolAddress((void**)&v_p,   g_v);
    cudaGetSymbolAddress((void**)&cc_p,  g_cc);
    bhalf *rp0, *rp1, *rp2, *xp0, *xp1, *xp2, *hp0, *hp1, *hp2;
    bhalf *wi0, *wi1, *wi2, *wd0, *wd1p, *wd2p;
    bhalf *wc10, *wc11, *wc12, *wc20, *wc21, *wc22;
    cudaGetSymbolAddress((void**)&rp0, g_rp0);
    cudaGetSymbolAddress((void**)&rp1, g_rp1);
    cudaGetSymbolAddress((void**)&rp2, g_rp2);
    cudaGetSymbolAddress((void**)&xp0, g_xp0);
    cudaGetSymbolAddress((void**)&xp1, g_xp1);
    cudaGetSymbolAddress((void**)&xp2, g_xp2);
    cudaGetSymbolAddress((void**)&hp0, g_hp0);
    cudaGetSymbolAddress((void**)&hp1, g_hp1);
    cudaGetSymbolAddress((void**)&hp2, g_hp2);
    cudaGetSymbolAddress((void**)&wi0, g_wi0);
    cudaGetSymbolAddress((void**)&wi1, g_wi1);
    cudaGetSymbolAddress((void**)&wi2, g_wi2);
    cudaGetSymbolAddress((void**)&wd0,  g_wdp0);
    cudaGetSymbolAddress((void**)&wd1p, g_wdp1);
    cudaGetSymbolAddress((void**)&wd2p, g_wdp2);
    cudaGetSymbolAddress((void**)&wc10, g_wc1p0);
    cudaGetSymbolAddress((void**)&wc11, g_wc1p1);
    cudaGetSymbolAddress((void**)&wc12, g_wc1p2);
    cudaGetSymbolAddress((void**)&wc20, g_wc2p0);
    cudaGetSymbolAddress((void**)&wc21, g_wc2p1);
    cudaGetSymbolAddress((void**)&wc22, g_wc2p2);

    // pack inputs & weights into triple-split planes
    pack3_kernel<<<512, 256>>>(x,   xp0, xp1, xp2, NB * SEQ * DIM);
    pack3_kernel<<<256, 256>>>(Wi,  wi0, wi1, wi2, DIM * DIM);
    pack3_wd1_kernel<<<256, 256>>>(Wd1, wd0, wd1p, wd2p);
    pack3_kernel<<<512, 256>>>(Wc1, wc10, wc11, wc12, 2 * DIM * CH);
    pack3_kernel<<<512, 256>>>(Wc2, wc20, wc21, wc22, CH * CH);

    dim3 blk(512);
    // init GEMM: tmp = x@Wi+bi  (M=8192, N=512, K=512)
    gemm6<<<dim3(DIM / BN, (NB * SEQ) / BM), blk, SMEM_BYTES>>>(
        xp0, xp1, xp2, wi0, wi1, wi2, bi, tmp_p, nullptr,
        nullptr, nullptr, nullptr,
        DIM, DIM, DIM, DIM, 0, 0, 0, 0, 0, 0, 0, 0);
    ln_init_kernel<<<NB * SEQ, 256>>>(g1, b1);
    init_state_kernel<<<NB, 32>>>();
    // u|v projection of initial rows (M=8192, N=1024, K=512)
    gemm6<<<dim3(2 * DIM / BN, (NB * SEQ) / BM), blk, SMEM_BYTES>>>(
        rp0, rp1, rp2, wd0, wd1p, wd2p, nullptr, u_p, v_p,
        nullptr, nullptr, nullptr,
        DIM, 0, 2 * DIM, DIM, 1, 0, SEQ, 1, 0, SEQ, 0, DIM);

    for (int step = 0; step < SEQ - 1; step++) {
        int S_cur = (SEQ - 1) - step;
        int Bc = (step == 0) ? 1 : BEAMK;
        int topk = S_cur < BEAMK ? S_cur : BEAMK;
        int base = SEQ + step * BEAMK;

        select_kernel<<<NB, 256>>>(Bc, S_cur, topk, base, bd1, Wd2, bd2);
        // cat GEMM: gelu([l|r]@Wc1+bc1) -> hcat planes (M=1280,N=2048,K=1024)
        gemm6<<<dim3(CH / BN, NTASK / BM), blk, SMEM_BYTES>>>(
            rp0, rp1, rp2, wc10, wc11, wc12, bc1, nullptr, nullptr,
            hp0, hp1, hp2,
            2 * DIM, 0, CH, CH, 2, 0, 0, 2, 0, 0, 1, 0);
        // GEMM2: cc = hcat@Wc2+bc2  (M=1280, N=2048, K=2048)
        gemm6<<<dim3(CH / BN, NTASK / BM), blk, SMEM_BYTES>>>(
            hp0, hp1, hp2, wc20, wc21, wc22, bc2, cc_p, nullptr,
            nullptr, nullptr, nullptr,
            CH, CH, CH, CH, 0, 0, 0, 0, 0, 0, 0, 0);
        gate_ln_kernel<<<NTASK, 256>>>(base, g2, b2);
        if (step < SEQ - 2) {
            // u|v projection of new rows (M=1280, N=1024, K=512)
            gemm6<<<dim3(2 * DIM / BN, NTASK / BM), blk, SMEM_BYTES>>>(
                rp0, rp1, rp2, wd0, wd1p, wd2p, nullptr, u_p, v_p,
                nullptr, nullptr, nullptr,
                DIM, 0, 2 * DIM, DIM, 1, base, BEAMK, 1, base, BEAMK, 0, DIM);
        }
    }

    final_kernel<<<NB, 256>>>(outp);
    (void)in_sizes; (void)n_in; (void)out_size;
}